// round 1
// baseline (speedup 1.0000x reference)
#include <cuda_runtime.h>

// Conv2d: x[32,128,56,56] (*) K[256,128,3,3], pad 1, stride 1, + scalar bias.
// Implicit GEMM: out[k][p] = sum_e W[k][e] * im2col(x)[e][p]
//   k in [0,256)  (output channels)
//   p in [0,100352) = n*3136 + oh*56 + ow
//   e in [0,1152)  = c*9 + r*3 + s   (matches OIHW contiguous layout of K)
// Tile: 128(k) x 128(p) x 8(e), 256 threads, 8x8 register micro-tile.

#define C_IN    128
#define H_IN    56
#define W_IN    56
#define K_OUT   256
#define HW      (H_IN * W_IN)       // 3136
#define E_TOT   (C_IN * 9)          // 1152
#define P_TOT   (32 * HW)           // 100352

#define TILE_K  128
#define TILE_P  128
#define TILE_E  8

__global__ __launch_bounds__(256, 2)
void conv2d_igemm_f32(const float* __restrict__ x,
                      const float* __restrict__ w,
                      const float* __restrict__ bias,
                      float* __restrict__ out) {
    __shared__ float As[TILE_E][TILE_K];   // weights, [e_local][k_local]
    __shared__ float Bs[TILE_E][TILE_P];   // im2col input, [e_local][p_local]

    const int tid = threadIdx.x;
    const int tx  = tid & 15;    // p micro-tile index
    const int ty  = tid >> 4;    // k micro-tile index
    const int k0  = blockIdx.y * TILE_K;
    const int p0  = blockIdx.x * TILE_P;

    // ---- per-thread B-load coords (p_local = tid % 128 is the same for all 4 loads) ----
    const int pl   = tid & 127;
    const int p    = p0 + pl;
    const int bn   = p / HW;
    const int phw  = p - bn * HW;
    const int boh  = phw / W_IN;
    const int bow  = phw - boh * W_IN;
    const float* xbase = x + (long long)bn * C_IN * HW;

    // ---- A-load coords: thread loads float4 of weights ----
    const int a_krow = tid >> 1;
    const int a_ecol = (tid & 1) * 4;
    const float* wrow = w + (long long)(k0 + a_krow) * E_TOT + a_ecol;

    float acc[8][8];
    #pragma unroll
    for (int i = 0; i < 8; i++)
        #pragma unroll
        for (int j = 0; j < 8; j++)
            acc[i][j] = 0.0f;

    for (int e0 = 0; e0 < E_TOT; e0 += TILE_E) {
        // load weight tile (coalesced float4, stored transposed into smem)
        float4 wv = *reinterpret_cast<const float4*>(wrow + e0);
        As[a_ecol + 0][a_krow] = wv.x;
        As[a_ecol + 1][a_krow] = wv.y;
        As[a_ecol + 2][a_krow] = wv.z;
        As[a_ecol + 3][a_krow] = wv.w;

        // load input tile (implicit im2col, coalesced along p)
        #pragma unroll
        for (int l = 0; l < 4; l++) {
            int kk = ((tid + l * 256) >> 7);       // 0..7
            int e  = e0 + kk;
            int c  = e / 9;
            int rs = e - c * 9;
            int r  = rs / 3;
            int s  = rs - r * 3;
            int ih = boh + r - 1;
            int iw = bow + s - 1;
            float v = 0.0f;
            if ((unsigned)ih < (unsigned)H_IN && (unsigned)iw < (unsigned)W_IN)
                v = xbase[(c * H_IN + ih) * W_IN + iw];
            Bs[kk][pl] = v;
        }
        __syncthreads();

        #pragma unroll
        for (int kk = 0; kk < TILE_E; kk++) {
            float a[8], b[8];
            #pragma unroll
            for (int j = 0; j < 8; j++) a[j] = As[kk][ty * 8 + j];
            #pragma unroll
            for (int j = 0; j < 8; j++) b[j] = Bs[kk][tx * 8 + j];
            #pragma unroll
            for (int i = 0; i < 8; i++)
                #pragma unroll
                for (int j = 0; j < 8; j++)
                    acc[i][j] = fmaf(a[i], b[j], acc[i][j]);
        }
        __syncthreads();
    }

    // ---- epilogue: scalar bias + NCHW scatter (coalesced along p within an image) ----
    const float bv = bias[0];
    #pragma unroll
    for (int i = 0; i < 8; i++) {
        int k = k0 + ty * 8 + i;
        #pragma unroll
        for (int j = 0; j < 8; j++) {
            int pp = p0 + tx * 8 + j;
            int n  = pp / HW;
            int hw = pp - n * HW;
            out[((long long)n * K_OUT + k) * HW + hw] = acc[i][j] + bv;
        }
    }
}

extern "C" void kernel_launch(void* const* d_in, const int* in_sizes, int n_in,
                              void* d_out, int out_size) {
    const float* x    = (const float*)d_in[0];
    const float* K    = (const float*)d_in[1];
    const float* bias = (const float*)d_in[2];
    float* out        = (float*)d_out;

    dim3 grid(P_TOT / TILE_P, K_OUT / TILE_K);   // (784, 2)
    conv2d_igemm_f32<<<grid, 256>>>(x, K, bias, out);
}